// round 2
// baseline (speedup 1.0000x reference)
#include <cuda_runtime.h>
#include <cstdint>

// ============================================================================
// ConvLSTMEncoder: the K=3 conv over a length-1 spatial dim reduces to the
// center tap W[:,:,1] -> this is a plain 3-layer LSTM.
//   B=256, T=512, CIN=64, H=128.  gates[b, 4H] = [in; h] @ Wc^T + bias
// Strategy: persistent kernel, 128 blocks (1/SM, all co-resident).
//   - 16 batch-groups x 8 gate-slice blocks. Each block owns 64 gate rows
//     (16 hidden units x 4 gates) per layer, weights resident in SMEM (fp32).
//   - h exchanged between the 8 blocks of a group via global double buffers,
//     synced by a monotonic per-group L2 counter barrier.
//   - Inner GEMV uses packed fma.rn.f32x2 (2 batch elems per op), with the
//     input vector stored pre-duplicated (z,z) in SMEM.
// ============================================================================

#define T_STEPS 512
#define CINX    64

static const int SMEM_BYTES = 223232;
// smem layout (bytes):
//   [0,      180224)  W^T slices: L0 192x64, L1 256x64, L2 256x64 (floats, [k][row])
//   [180224, 215040)  zdup: 256 * 17 u64 ((z,z) pairs, padded stride 17)
//   [215040, 219392)  gbuf: 64 x 17 floats (padded)
//   [219392, 220160)  bias: 3 x 64 floats
//   [220160, 223232)  c state: 3 x 256 floats

__device__ float    g_hbuf[3 * 2 * 128 * 256];  // [layer][parity][unit][batch]
__device__ unsigned g_ctr[16];                  // per-group barrier counters

__global__ void reset_ctr_kernel() {
    if (threadIdx.x < 16) g_ctr[threadIdx.x] = 0u;
}

__device__ __forceinline__ unsigned long long pack2f(float v) {
    unsigned u = __float_as_uint(v);
    return ((unsigned long long)u << 32) | (unsigned long long)u;
}
__device__ __forceinline__ float lo32(unsigned long long p) { return __uint_as_float((unsigned)p); }
__device__ __forceinline__ float hi32(unsigned long long p) { return __uint_as_float((unsigned)(p >> 32)); }

__device__ __forceinline__ float fast_rcp(float x) {
    float r; asm("rcp.approx.f32 %0, %1;" : "=f"(r) : "f"(x)); return r;
}
__device__ __forceinline__ float sigm(float x) {
    return fast_rcp(1.0f + __expf(-x));
}
__device__ __forceinline__ float tanh_f(float x) {
    x = fminf(fmaxf(x, -15.0f), 15.0f);
    float e = __expf(-2.0f * x);
    return (1.0f - e) * fast_rcp(1.0f + e);
}

#define FMA2(acc, a, b) asm("fma.rn.f32x2 %0, %1, %2, %0;" : "+l"(acc) : "l"(a), "l"(b))

// Barrier among the 8 blocks of one batch-group. Monotonic counter; target
// grows by 8 each phase. Counters reset by reset_ctr_kernel each launch.
__device__ __forceinline__ void group_barrier(int grp, unsigned target) {
    __syncthreads();
    if (threadIdx.x == 0) {
        __threadfence();
        atomicAdd(&g_ctr[grp], 1u);
        unsigned v;
        for (;;) {
            asm volatile("ld.global.acquire.gpu.u32 %0, [%1];"
                         : "=r"(v) : "l"(&g_ctr[grp]) : "memory");
            if (v >= target) break;
            __nanosleep(32);
        }
    }
    __syncthreads();
}

template<int KD>
__device__ __forceinline__ void matmul_slice(const float* __restrict__ Wl,
                                             const unsigned long long* __restrict__ zb,
                                             unsigned long long& a00, unsigned long long& a01,
                                             unsigned long long& a10, unsigned long long& a11) {
#pragma unroll 8
    for (int k = 0; k < KD; k++) {
        ulonglong2 w = *(const ulonglong2*)(Wl + (k << 6));  // rows 4q..4q+3, col k
        unsigned long long z0 = zb[k * 17];
        unsigned long long z1 = zb[k * 17 + 1];
        FMA2(a00, w.x, z0); FMA2(a01, w.x, z1);
        FMA2(a10, w.y, z0); FMA2(a11, w.y, z1);
    }
}

__global__ void __launch_bounds__(128, 1) convlstm_kernel(
    const float* __restrict__ x,
    const float* __restrict__ W1, const float* __restrict__ b1,
    const float* __restrict__ W2, const float* __restrict__ b2,
    const float* __restrict__ W3, const float* __restrict__ b3,
    const float* __restrict__ h1i, const float* __restrict__ c1i,
    const float* __restrict__ h2i, const float* __restrict__ c2i,
    const float* __restrict__ h3i, const float* __restrict__ c3i,
    float* __restrict__ out)
{
    extern __shared__ unsigned char smraw[];
    float*              Wsm  = (float*)smraw;
    unsigned long long* zd   = (unsigned long long*)(smraw + 180224);
    float*              gbuf = (float*)(smraw + 215040);
    float*              bias = (float*)(smraw + 219392);
    float*              c_s  = (float*)(smraw + 220160);

    const int tid = threadIdx.x;
    const int gid = blockIdx.x & 7;    // gate-slice id (0..7): hidden units [16*gid, 16*gid+16)
    const int bg  = blockIdx.x >> 3;   // batch group (0..15): batches [16*bg, 16*bg+16)
    const int bgb = bg << 4;

    // ---- Prologue: load weight slices (center tap), transposed to [k][row64] ----
    for (int idx = tid; idx < 192 * 64; idx += 128) {
        int k = idx >> 6, r = idx & 63;
        int grow = ((r >> 4) << 7) | (gid << 4) | (r & 15);  // gate*128 + gid*16 + u
        Wsm[idx] = W1[(size_t)grow * 576 + k * 3 + 1];
    }
    for (int idx = tid; idx < 256 * 64; idx += 128) {
        int k = idx >> 6, r = idx & 63;
        int grow = ((r >> 4) << 7) | (gid << 4) | (r & 15);
        Wsm[12288 + idx] = W2[(size_t)grow * 768 + k * 3 + 1];
        Wsm[28672 + idx] = W3[(size_t)grow * 768 + k * 3 + 1];
    }
    for (int idx = tid; idx < 192; idx += 128) {
        int L = idx >> 6, r = idx & 63;
        int grow = ((r >> 4) << 7) | (gid << 4) | (r & 15);
        const float* bp_ = (L == 0) ? b1 : (L == 1) ? b2 : b3;
        bias[idx] = bp_[grow];
    }
    // init c (smem) and h (global parity-1 buffers, read at t=0)
    for (int ci = tid; ci < 256; ci += 128) {
        int u = ci >> 4, b = ci & 15;
        int gidx = (bgb + b) * 128 + (gid << 4) + u;   // (B,128,1) layout
        c_s[ci]       = c1i[gidx];
        c_s[256 + ci] = c2i[gidx];
        c_s[512 + ci] = c3i[gidx];
        int hb = ((gid << 4) + u) * 256 + bgb + b;
        g_hbuf[(0 * 2 + 1) * 32768 + hb] = h1i[gidx];
        g_hbuf[(1 * 2 + 1) * 32768 + hb] = h2i[gidx];
        g_hbuf[(2 * 2 + 1) * 32768 + hb] = h3i[gidx];
    }
    unsigned phase = 1;
    group_barrier(bg, 8u * phase); phase++;

    const int q = tid & 15, bp2 = tid >> 4;  // row-quad, batch-pair

    for (int t = 0; t < T_STEPS; t++) {
        const int pc = t & 1, pp = pc ^ 1;
        for (int L = 0; L < 3; L++) {
            // ---- assemble duplicated input vector zdup[k][b] = (z,z) ----
            if (L == 0) {
                const float* xb = x + (size_t)bgb * (T_STEPS * CINX) + (size_t)t * CINX;
                for (int idx = tid; idx < 1024; idx += 128) {
                    int b = idx >> 6, k = idx & 63;
                    float v = __ldg(&xb[(size_t)b * (T_STEPS * CINX) + k]);
                    zd[k * 17 + b] = pack2f(v);
                }
                const float* s1 = &g_hbuf[(0 * 2 + pp) * 32768 + bgb];
                for (int idx = tid; idx < 2048; idx += 128) {
                    int k = idx >> 4, b = idx & 15;
                    zd[(64 + k) * 17 + b] = pack2f(__ldcg(&s1[k * 256 + b]));
                }
            } else {
                const float* s0 = &g_hbuf[((L - 1) * 2 + pc) * 32768 + bgb];  // h_{L-1}(t)
                const float* s1 = &g_hbuf[(L * 2 + pp) * 32768 + bgb];        // h_L(t-1)
                for (int idx = tid; idx < 2048; idx += 128) {
                    int k = idx >> 4, b = idx & 15;
                    zd[k * 17 + b]         = pack2f(__ldcg(&s0[k * 256 + b]));
                    zd[(128 + k) * 17 + b] = pack2f(__ldcg(&s1[k * 256 + b]));
                }
            }
            __syncthreads();

            // ---- GEMV slice: 64 gate rows x 16 batch, f32x2 packed ----
            unsigned long long a00 = 0, a01 = 0, a10 = 0, a11 = 0;
            const unsigned long long* zb = zd + 2 * bp2;
            if (L == 0)      matmul_slice<192>(Wsm + 4 * q,         zb, a00, a01, a10, a11);
            else if (L == 1) matmul_slice<256>(Wsm + 12288 + 4 * q, zb, a00, a01, a10, a11);
            else             matmul_slice<256>(Wsm + 28672 + 4 * q, zb, a00, a01, a10, a11);

            int r0 = q << 2, bb = bp2 << 1;
            gbuf[(r0 + 0) * 17 + bb]     = lo32(a00);
            gbuf[(r0 + 1) * 17 + bb]     = hi32(a00);
            gbuf[(r0 + 0) * 17 + bb + 1] = lo32(a01);
            gbuf[(r0 + 1) * 17 + bb + 1] = hi32(a01);
            gbuf[(r0 + 2) * 17 + bb]     = lo32(a10);
            gbuf[(r0 + 3) * 17 + bb]     = hi32(a10);
            gbuf[(r0 + 2) * 17 + bb + 1] = lo32(a11);
            gbuf[(r0 + 3) * 17 + bb + 1] = hi32(a11);
            __syncthreads();

            // ---- LSTM cell update for 16 units x 16 batch ----
            float* cL = c_s + L * 256;
            float* hdst = &g_hbuf[(L * 2 + pc) * 32768 + bgb];
            const float* bL = bias + L * 64;
            for (int ci = tid; ci < 256; ci += 128) {
                int u = ci >> 4, b = ci & 15;
                float gi = gbuf[u * 17 + b]        + bL[u];
                float gf = gbuf[(16 + u) * 17 + b] + bL[16 + u];
                float go = gbuf[(32 + u) * 17 + b] + bL[32 + u];
                float gg = gbuf[(48 + u) * 17 + b] + bL[48 + u];
                float c  = cL[ci];
                float cn = sigm(gf) * c + sigm(gi) * tanh_f(gg);
                float hn = sigm(go) * tanh_f(cn);
                cL[ci] = cn;
                hdst[((gid << 4) + u) * 256 + b] = hn;
                if (L == 2 && t == T_STEPS - 1)
                    out[(size_t)(bgb + b) * 128 + (gid << 4) + u] = hn;
            }
            group_barrier(bg, 8u * phase); phase++;
        }
    }
}

extern "C" void kernel_launch(void* const* d_in, const int* in_sizes, int n_in,
                              void* d_out, int out_size) {
    (void)in_sizes; (void)n_in; (void)out_size;
    const float* x  = (const float*)d_in[0];
    const float* W1 = (const float*)d_in[1];
    const float* b1 = (const float*)d_in[2];
    const float* W2 = (const float*)d_in[3];
    const float* b2 = (const float*)d_in[4];
    const float* W3 = (const float*)d_in[5];
    const float* b3 = (const float*)d_in[6];
    const float* h1 = (const float*)d_in[7];
    const float* c1 = (const float*)d_in[8];
    const float* h2 = (const float*)d_in[9];
    const float* c2 = (const float*)d_in[10];
    const float* h3 = (const float*)d_in[11];
    const float* c3 = (const float*)d_in[12];
    float* out = (float*)d_out;

    cudaFuncSetAttribute(convlstm_kernel,
                         cudaFuncAttributeMaxDynamicSharedMemorySize, SMEM_BYTES);
    reset_ctr_kernel<<<1, 32>>>();
    convlstm_kernel<<<128, 128, SMEM_BYTES>>>(x, W1, b1, W2, b2, W3, b3,
                                              h1, c1, h2, c2, h3, c3, out);
}